// round 6
// baseline (speedup 1.0000x reference)
#include <cuda_runtime.h>
#include <cstdint>

// SoftTree: x[4096,512], gw[512,255], gb[255], pw[64,512,256], pb[64,256]
// out[b,o] = sum_l leafp[b,l] * ((x @ pw[o])[b,l] + pb[o,l])
//
// R6 vs R5: GEMM goes 256 -> 512 threads (16 warps), warp tile 64x64 ->
// 32x64, acc 128 -> 64 regs/thread. Same CTA tile 128x256xK512, same
// double-buffered cp.async. Goal: occupancy 12.5% -> 25%, tensor 52% -> ~80%.

#define N_BATCH   4096
#define N_IN      512
#define N_OUT     64
#define N_LEAF    256
#define N_GATE    255
#define TREE_DEPTH 8

__device__ float d_leafp[N_BATCH * N_LEAF];                    // 4 MB
__device__ float d_pwc[(size_t)N_OUT * N_IN * N_LEAF];         // 33.5 MB
__device__ float d_xt[N_BATCH * N_IN];                         // 8 MB

__device__ __forceinline__ float rna_tf32(float f) {
    uint32_t u;
    asm("cvt.rna.tf32.f32 %0, %1;" : "=r"(u) : "f"(f));
    return __uint_as_float(u);
}

__device__ __forceinline__ uint32_t smem_u32(const void* p) {
    uint32_t a;
    asm("{ .reg .u64 t; cvta.to.shared.u64 t, %1; cvt.u32.u64 %0, t; }"
        : "=r"(a) : "l"(p));
    return a;
}

#define CP_ASYNC16(dst_u32, src_ptr) \
    asm volatile("cp.async.cg.shared.global [%0], [%1], 16;" \
                 :: "r"(dst_u32), "l"(src_ptr))
#define CP_COMMIT()  asm volatile("cp.async.commit_group;" ::: "memory")
#define CP_WAIT1()   asm volatile("cp.async.wait_group 1;" ::: "memory")

__device__ __forceinline__ void mma_tf32(float* d, const uint32_t* a,
                                         const uint32_t* b) {
    asm volatile(
        "mma.sync.aligned.m16n8k8.row.col.f32.tf32.tf32.f32 "
        "{%0,%1,%2,%3}, {%4,%5,%6,%7}, {%8,%9}, {%0,%1,%2,%3};"
        : "+f"(d[0]), "+f"(d[1]), "+f"(d[2]), "+f"(d[3])
        : "r"(a[0]), "r"(a[1]), "r"(a[2]), "r"(a[3]), "r"(b[0]), "r"(b[1]));
}

// ---------------------------------------------------------------------------
// K0: rna-round x;  K1: rna-round pw (layout preserved)
// ---------------------------------------------------------------------------
__global__ __launch_bounds__(256) void xt_kernel(const float* __restrict__ x) {
    int i = blockIdx.x * 256 + threadIdx.x;
    float4 v = reinterpret_cast<const float4*>(x)[i];
    v.x = rna_tf32(v.x); v.y = rna_tf32(v.y);
    v.z = rna_tf32(v.z); v.w = rna_tf32(v.w);
    reinterpret_cast<float4*>(d_xt)[i] = v;
}
__global__ __launch_bounds__(256) void pwc_kernel(const float* __restrict__ pw) {
    int i = blockIdx.x * 256 + threadIdx.x;
    float4 v = reinterpret_cast<const float4*>(pw)[i];
    v.x = rna_tf32(v.x); v.y = rna_tf32(v.y);
    v.z = rna_tf32(v.z); v.w = rna_tf32(v.w);
    reinterpret_cast<float4*>(d_pwc)[i] = v;
}

// ---------------------------------------------------------------------------
// K2: gates + leaf probabilities (proven)
// ---------------------------------------------------------------------------
#define K1_ROWS 8
__global__ __launch_bounds__(256) void softtree_gates_kernel(
    const float* __restrict__ x, const float* __restrict__ gw,
    const float* __restrict__ gb)
{
    __shared__ float xs[K1_ROWS][N_IN];
    __shared__ float gs[K1_ROWS][N_LEAF];
    const int tid = threadIdx.x;
    const int b0  = blockIdx.x * K1_ROWS;

    {
        const float4* src = reinterpret_cast<const float4*>(x + (size_t)b0 * N_IN);
        float4* dst = reinterpret_cast<float4*>(&xs[0][0]);
        #pragma unroll
        for (int it = 0; it < (K1_ROWS * N_IN / 4) / 256; ++it)
            dst[it * 256 + tid] = src[it * 256 + tid];
    }
    __syncthreads();

    if (tid < N_GATE) {
        float acc[K1_ROWS];
        const float bias = gb[tid];
        #pragma unroll
        for (int r = 0; r < K1_ROWS; ++r) acc[r] = bias;
        #pragma unroll 4
        for (int i = 0; i < N_IN; ++i) {
            float w = gw[i * N_GATE + tid];
            #pragma unroll
            for (int r = 0; r < K1_ROWS; ++r)
                acc[r] = fmaf(xs[r][i], w, acc[r]);
        }
        #pragma unroll
        for (int r = 0; r < K1_ROWS; ++r)
            gs[r][tid] = 1.0f / (1.0f + expf(-acc[r]));
    }
    __syncthreads();

    const int l = tid;
    #pragma unroll
    for (int r = 0; r < K1_ROWS; ++r) {
        float p = 1.0f;
        int index = 1;
        #pragma unroll
        for (int j = 0; j < TREE_DEPTH; ++j) {
            int bit = (l >> (TREE_DEPTH - 1 - j)) & 1;
            float g = gs[r][index - 1];
            p *= bit ? (1.0f - g) : g;
            index = 2 * index + bit;
        }
        d_leafp[(size_t)(b0 + r) * N_LEAF + l] = p;
    }
}

// ---------------------------------------------------------------------------
// K3: tf32 mma.sync GEMM + fused epilogue.
// Grid (32 batch-tiles, 64 heads) = 2048 CTAs, 512 threads (16 warps, 4m x 4n).
// CTA tile M=128, N=256, BK=32 (4 k-steps of 8), cp.async double-buffered.
// Warp tile 32x64: 2 m-frags x 8 n-frags, acc[2][8][4] = 64 regs.
// ---------------------------------------------------------------------------
#define BM 128
#define BN 256
#define BK 32
#define A_STRIDE 36
#define B_STRIDE 260
#define A_STAGE (BM * A_STRIDE)
#define B_STAGE (BK * B_STRIDE)
#define SMEM_FLOATS (2 * A_STAGE + 2 * B_STAGE + 4 * BM)
#define N_STAGE 16      // K / BK

__global__ __launch_bounds__(512, 1) void softtree_gemm_mma(
    const float* __restrict__ pb, float* __restrict__ out)
{
    extern __shared__ float sm[];
    float* As  = sm;
    float* Bs  = sm + 2 * A_STAGE;
    float* red = sm + 2 * A_STAGE + 2 * B_STAGE;  // [4][BM]

    const int tid  = threadIdx.x;
    const int lane = tid & 31;
    const int wid  = tid >> 5;
    const int wm   = wid >> 2;          // 0..3 -> 32-row group
    const int wn   = wid & 3;           // 0..3 -> 64-col group
    const int lq   = lane >> 2;         // 0..7
    const int lr   = lane & 3;          // 0..3
    const int o    = blockIdx.y;
    const int b0   = blockIdx.x * BM;

    const float* __restrict__ pwo = d_pwc + (size_t)o * N_IN * N_LEAF;

    // A: 1024 ld16 over 512 threads -> 2 iters; B: 2048 ld16 -> 4 iters.
    auto load_stage = [&](int kt) {
        const int s = kt & 1;
        const int k0 = kt * BK;
        uint32_t a_base = smem_u32(As + s * A_STAGE);
        uint32_t b_base = smem_u32(Bs + s * B_STAGE);
        #pragma unroll
        for (int it = 0; it < 2; ++it) {
            int idx = it * 512 + tid;
            int m = idx >> 3, kq = idx & 7;
            CP_ASYNC16(a_base + (uint32_t)(m * A_STRIDE + 4 * kq) * 4,
                       d_xt + (size_t)(b0 + m) * N_IN + k0 + 4 * kq);
        }
        #pragma unroll
        for (int it = 0; it < 4; ++it) {
            int idx = it * 512 + tid;
            int k = idx >> 6, nq = idx & 63;
            CP_ASYNC16(b_base + (uint32_t)(k * B_STRIDE + 4 * nq) * 4,
                       pwo + (size_t)(k0 + k) * N_LEAF + 4 * nq);
        }
        CP_COMMIT();
    };

    float acc[2][8][4];
    #pragma unroll
    for (int mf = 0; mf < 2; ++mf)
        #pragma unroll
        for (int nf = 0; nf < 8; ++nf)
            #pragma unroll
            for (int e = 0; e < 4; ++e) acc[mf][nf][e] = 0.0f;

    load_stage(0);
    load_stage(1);

    for (int kt = 0; kt < N_STAGE; ++kt) {
        CP_WAIT1();
        __syncthreads();

        const int s = kt & 1;
        const float* Ab = As + s * A_STAGE + (wm * 32) * A_STRIDE;
        const float* Bb = Bs + s * B_STAGE;

        #pragma unroll
        for (int ks = 0; ks < 4; ++ks) {
            const int kk = ks * 8;
            uint32_t af[2][4], bf[8][2];
            #pragma unroll
            for (int mf = 0; mf < 2; ++mf) {
                const float* ap = Ab + (mf * 16 + lq) * A_STRIDE + kk + lr;
                af[mf][0] = __float_as_uint(ap[0]);
                af[mf][1] = __float_as_uint(ap[8 * A_STRIDE]);
                af[mf][2] = __float_as_uint(ap[4]);
                af[mf][3] = __float_as_uint(ap[8 * A_STRIDE + 4]);
            }
            #pragma unroll
            for (int nf = 0; nf < 8; ++nf) {
                const float* bp = Bb + (kk + lr) * B_STRIDE + wn * 64 + nf * 8 + lq;
                bf[nf][0] = __float_as_uint(bp[0]);
                bf[nf][1] = __float_as_uint(bp[4 * B_STRIDE]);
            }
            #pragma unroll
            for (int mf = 0; mf < 2; ++mf)
                #pragma unroll
                for (int nf = 0; nf < 8; ++nf)
                    mma_tf32(acc[mf][nf], af[mf], bf[nf]);
        }

        __syncthreads();
        if (kt + 2 < N_STAGE) load_stage(kt + 2);
    }

    // Fused epilogue: per-fragment, rows r0=wm*32+mf*16+lq, r1=r0+8;
    // cols n = wn*64 + nf*8 + 2*lr (+1). Reduce over lr, then over wn in smem.
    const float* __restrict__ pbo = pb + (size_t)o * N_LEAF;
    #pragma unroll
    for (int mf = 0; mf < 2; ++mf) {
        const int r0 = wm * 32 + mf * 16 + lq;
        const int r1 = r0 + 8;
        const float* p0row = d_leafp + (size_t)(b0 + r0) * N_LEAF;
        const float* p1row = d_leafp + (size_t)(b0 + r1) * N_LEAF;
        float s0 = 0.0f, s1 = 0.0f;
        #pragma unroll
        for (int nf = 0; nf < 8; ++nf) {
            const int n = wn * 64 + nf * 8 + 2 * lr;
            float2 pbv = *reinterpret_cast<const float2*>(pbo + n);
            float2 pa  = *reinterpret_cast<const float2*>(p0row + n);
            float2 pc  = *reinterpret_cast<const float2*>(p1row + n);
            s0 = fmaf(acc[mf][nf][0] + pbv.x, pa.x, s0);
            s0 = fmaf(acc[mf][nf][1] + pbv.y, pa.y, s0);
            s1 = fmaf(acc[mf][nf][2] + pbv.x, pc.x, s1);
            s1 = fmaf(acc[mf][nf][3] + pbv.y, pc.y, s1);
        }
        s0 += __shfl_xor_sync(0xffffffffu, s0, 1);
        s0 += __shfl_xor_sync(0xffffffffu, s0, 2);
        s1 += __shfl_xor_sync(0xffffffffu, s1, 1);
        s1 += __shfl_xor_sync(0xffffffffu, s1, 2);
        if (lr == 0) {
            red[wn * BM + r0] = s0;
            red[wn * BM + r1] = s1;
        }
    }
    __syncthreads();

    if (tid < BM) {
        float v = red[0 * BM + tid] + red[1 * BM + tid] +
                  red[2 * BM + tid] + red[3 * BM + tid];
        out[(size_t)(b0 + tid) * N_OUT + o] = v;
    }
}

// ---------------------------------------------------------------------------
extern "C" void kernel_launch(void* const* d_in, const int* in_sizes, int n_in,
                              void* d_out, int out_size)
{
    const float* x  = (const float*)d_in[0];
    const float* gw = (const float*)d_in[1];
    const float* gb = (const float*)d_in[2];
    const float* pw = (const float*)d_in[3];
    const float* pb = (const float*)d_in[4];
    float* out = (float*)d_out;

    const int smem_bytes = SMEM_FLOATS * 4;
    cudaFuncSetAttribute(softtree_gemm_mma,
                         cudaFuncAttributeMaxDynamicSharedMemorySize, smem_bytes);

    xt_kernel<<<(N_BATCH * N_IN / 4) / 256, 256>>>(x);
    pwc_kernel<<<((size_t)N_OUT * N_IN * N_LEAF / 4) / 256, 256>>>(pw);
    softtree_gates_kernel<<<N_BATCH / K1_ROWS, 256>>>(x, gw, gb);

    dim3 grid(N_BATCH / BM, N_OUT);
    softtree_gemm_mma<<<grid, 512, smem_bytes>>>(pb, out);
}

// round 7
// speedup vs baseline: 1.1055x; 1.1055x over previous
#include <cuda_runtime.h>
#include <cstdint>

// SoftTree: x[4096,512], gw[512,255], gb[255], pw[64,512,256], pb[64,256]
// out[b,o] = sum_l leafp[b,l] * ((x @ pw[o])[b,l] + pb[o,l])
//
// R7 vs R5 (R6 tiling regression reverted):
//  - GEMM back to 256 thr / 8 warps / 64x64 warp tile (best LDS-per-MMA).
//  - 4-stage cp.async ring: ONE __syncthreads per K-stage (was 2), loads for
//    kt+3 issued right after the barrier (3-deep prefetch).
//  - rna_tf32 rounding fused into the GEMM fragment path; xt/pwc prep
//    kernels and 41.5 MB scratch deleted. GEMM reads x/pw directly.

#define N_BATCH   4096
#define N_IN      512
#define N_OUT     64
#define N_LEAF    256
#define N_GATE    255
#define TREE_DEPTH 8

__device__ float d_leafp[N_BATCH * N_LEAF];   // 4 MB scratch

__device__ __forceinline__ uint32_t rna_tf32_u(float f) {
    uint32_t u;
    asm("cvt.rna.tf32.f32 %0, %1;" : "=r"(u) : "f"(f));
    return u;
}

__device__ __forceinline__ uint32_t smem_u32(const void* p) {
    uint32_t a;
    asm("{ .reg .u64 t; cvta.to.shared.u64 t, %1; cvt.u32.u64 %0, t; }"
        : "=r"(a) : "l"(p));
    return a;
}

#define CP_ASYNC16(dst_u32, src_ptr) \
    asm volatile("cp.async.cg.shared.global [%0], [%1], 16;" \
                 :: "r"(dst_u32), "l"(src_ptr))
#define CP_COMMIT()  asm volatile("cp.async.commit_group;" ::: "memory")
#define CP_WAIT2()   asm volatile("cp.async.wait_group 2;" ::: "memory")

__device__ __forceinline__ void mma_tf32(float* d, const uint32_t* a,
                                         const uint32_t* b) {
    asm volatile(
        "mma.sync.aligned.m16n8k8.row.col.f32.tf32.tf32.f32 "
        "{%0,%1,%2,%3}, {%4,%5,%6,%7}, {%8,%9}, {%0,%1,%2,%3};"
        : "+f"(d[0]), "+f"(d[1]), "+f"(d[2]), "+f"(d[3])
        : "r"(a[0]), "r"(a[1]), "r"(a[2]), "r"(a[3]), "r"(b[0]), "r"(b[1]));
}

// ---------------------------------------------------------------------------
// K2: gates + leaf probabilities (proven)
// ---------------------------------------------------------------------------
#define K1_ROWS 8
__global__ __launch_bounds__(256) void softtree_gates_kernel(
    const float* __restrict__ x, const float* __restrict__ gw,
    const float* __restrict__ gb)
{
    __shared__ float xs[K1_ROWS][N_IN];
    __shared__ float gs[K1_ROWS][N_LEAF];
    const int tid = threadIdx.x;
    const int b0  = blockIdx.x * K1_ROWS;

    {
        const float4* src = reinterpret_cast<const float4*>(x + (size_t)b0 * N_IN);
        float4* dst = reinterpret_cast<float4*>(&xs[0][0]);
        #pragma unroll
        for (int it = 0; it < (K1_ROWS * N_IN / 4) / 256; ++it)
            dst[it * 256 + tid] = src[it * 256 + tid];
    }
    __syncthreads();

    if (tid < N_GATE) {
        float acc[K1_ROWS];
        const float bias = gb[tid];
        #pragma unroll
        for (int r = 0; r < K1_ROWS; ++r) acc[r] = bias;
        #pragma unroll 4
        for (int i = 0; i < N_IN; ++i) {
            float w = gw[i * N_GATE + tid];
            #pragma unroll
            for (int r = 0; r < K1_ROWS; ++r)
                acc[r] = fmaf(xs[r][i], w, acc[r]);
        }
        #pragma unroll
        for (int r = 0; r < K1_ROWS; ++r)
            gs[r][tid] = 1.0f / (1.0f + expf(-acc[r]));
    }
    __syncthreads();

    const int l = tid;
    #pragma unroll
    for (int r = 0; r < K1_ROWS; ++r) {
        float p = 1.0f;
        int index = 1;
        #pragma unroll
        for (int j = 0; j < TREE_DEPTH; ++j) {
            int bit = (l >> (TREE_DEPTH - 1 - j)) & 1;
            float g = gs[r][index - 1];
            p *= bit ? (1.0f - g) : g;
            index = 2 * index + bit;
        }
        d_leafp[(size_t)(b0 + r) * N_LEAF + l] = p;
    }
}

// ---------------------------------------------------------------------------
// K3: tf32 mma.sync GEMM + fused epilogue.
// Grid (32 batch-tiles, 64 heads), 256 threads (8 warps, 2m x 4n).
// CTA tile M=128, N=256, BK=32; 4-stage cp.async ring, 1 barrier/stage.
// Warp tile 64x64: acc[4][8][4]. rna-rounding applied to fragments.
// ---------------------------------------------------------------------------
#define BM 128
#define BN 256
#define BK 32
#define A_STRIDE 36
#define B_STRIDE 260
#define A_STAGE (BM * A_STRIDE)
#define B_STAGE (BK * B_STRIDE)
#define STAGE_FLOATS (A_STAGE + B_STAGE)
#define N_STAGES 4
#define SMEM_FLOATS (N_STAGES * STAGE_FLOATS + 4 * BM)
#define N_KT 16      // K / BK

__global__ __launch_bounds__(256, 1) void softtree_gemm_mma(
    const float* __restrict__ x, const float* __restrict__ pw,
    const float* __restrict__ pb, float* __restrict__ out)
{
    extern __shared__ float sm[];
    float* red = sm + N_STAGES * STAGE_FLOATS;  // [4][BM]

    const int tid  = threadIdx.x;
    const int lane = tid & 31;
    const int wid  = tid >> 5;
    const int wm   = wid >> 2;          // 0..1
    const int wn   = wid & 3;           // 0..3
    const int lq   = lane >> 2;         // 0..7
    const int lr   = lane & 3;          // 0..3
    const int o    = blockIdx.y;
    const int b0   = blockIdx.x * BM;

    const float* __restrict__ pwo = pw + (size_t)o * N_IN * N_LEAF;

    auto load_stage = [&](int kt) {
        const int s = kt & (N_STAGES - 1);
        const int k0 = kt * BK;
        uint32_t a_base = smem_u32(sm + s * STAGE_FLOATS);
        uint32_t b_base = a_base + A_STAGE * 4;
        #pragma unroll
        for (int it = 0; it < 4; ++it) {
            int idx = it * 256 + tid;
            int m = idx >> 3, kq = idx & 7;
            CP_ASYNC16(a_base + (uint32_t)(m * A_STRIDE + 4 * kq) * 4,
                       x + (size_t)(b0 + m) * N_IN + k0 + 4 * kq);
        }
        #pragma unroll
        for (int it = 0; it < 8; ++it) {
            int idx = it * 256 + tid;
            int k = idx >> 6, nq = idx & 63;
            CP_ASYNC16(b_base + (uint32_t)(k * B_STRIDE + 4 * nq) * 4,
                       pwo + (size_t)(k0 + k) * N_LEAF + 4 * nq);
        }
        CP_COMMIT();
    };

    float acc[4][8][4];
    #pragma unroll
    for (int mf = 0; mf < 4; ++mf)
        #pragma unroll
        for (int nf = 0; nf < 8; ++nf)
            #pragma unroll
            for (int e = 0; e < 4; ++e) acc[mf][nf][e] = 0.0f;

    load_stage(0);
    load_stage(1);
    load_stage(2);

    for (int kt = 0; kt < N_KT; ++kt) {
        CP_WAIT2();          // stage kt complete (<=2 groups pending)
        __syncthreads();     // make cp.async data visible CTA-wide

        // Prefetch kt+3 into buffer (kt-1)%4 — all warps finished reading it
        // before the barrier above.
        if (kt + 3 < N_KT) load_stage(kt + 3);

        const int s = kt & (N_STAGES - 1);
        const float* Ab = sm + s * STAGE_FLOATS + (wm * 64) * A_STRIDE;
        const float* Bb = sm + s * STAGE_FLOATS + A_STAGE;

        #pragma unroll
        for (int ks = 0; ks < 4; ++ks) {
            const int kk = ks * 8;
            uint32_t af[4][4], bf[8][2];
            #pragma unroll
            for (int mf = 0; mf < 4; ++mf) {
                const float* ap = Ab + (mf * 16 + lq) * A_STRIDE + kk + lr;
                af[mf][0] = rna_tf32_u(ap[0]);
                af[mf][1] = rna_tf32_u(ap[8 * A_STRIDE]);
                af[mf][2] = rna_tf32_u(ap[4]);
                af[mf][3] = rna_tf32_u(ap[8 * A_STRIDE + 4]);
            }
            #pragma unroll
            for (int nf = 0; nf < 8; ++nf) {
                const float* bp = Bb + (kk + lr) * B_STRIDE + wn * 64 + nf * 8 + lq;
                bf[nf][0] = rna_tf32_u(bp[0]);
                bf[nf][1] = rna_tf32_u(bp[4 * B_STRIDE]);
            }
            #pragma unroll
            for (int mf = 0; mf < 4; ++mf)
                #pragma unroll
                for (int nf = 0; nf < 8; ++nf)
                    mma_tf32(acc[mf][nf], af[mf], bf[nf]);
        }
    }

    // Fused epilogue: s[row] = sum_n p[b,n]*(C[b,n] + pb[o,n])
    const float* __restrict__ pbo = pb + (size_t)o * N_LEAF;
    #pragma unroll
    for (int mf = 0; mf < 4; ++mf) {
        const int r0 = wm * 64 + mf * 16 + lq;
        const int r1 = r0 + 8;
        const float* p0row = d_leafp + (size_t)(b0 + r0) * N_LEAF;
        const float* p1row = d_leafp + (size_t)(b0 + r1) * N_LEAF;
        float s0 = 0.0f, s1 = 0.0f;
        #pragma unroll
        for (int nf = 0; nf < 8; ++nf) {
            const int n = wn * 64 + nf * 8 + 2 * lr;
            float2 pbv = *reinterpret_cast<const float2*>(pbo + n);
            float2 pa  = *reinterpret_cast<const float2*>(p0row + n);
            float2 pc  = *reinterpret_cast<const float2*>(p1row + n);
            s0 = fmaf(acc[mf][nf][0] + pbv.x, pa.x, s0);
            s0 = fmaf(acc[mf][nf][1] + pbv.y, pa.y, s0);
            s1 = fmaf(acc[mf][nf][2] + pbv.x, pc.x, s1);
            s1 = fmaf(acc[mf][nf][3] + pbv.y, pc.y, s1);
        }
        s0 += __shfl_xor_sync(0xffffffffu, s0, 1);
        s0 += __shfl_xor_sync(0xffffffffu, s0, 2);
        s1 += __shfl_xor_sync(0xffffffffu, s1, 1);
        s1 += __shfl_xor_sync(0xffffffffu, s1, 2);
        if (lr == 0) {
            red[wn * BM + r0] = s0;
            red[wn * BM + r1] = s1;
        }
    }
    __syncthreads();

    if (tid < BM) {
        float v = red[0 * BM + tid] + red[1 * BM + tid] +
                  red[2 * BM + tid] + red[3 * BM + tid];
        out[(size_t)(b0 + tid) * N_OUT + o] = v;
    }
}

// ---------------------------------------------------------------------------
extern "C" void kernel_launch(void* const* d_in, const int* in_sizes, int n_in,
                              void* d_out, int out_size)
{
    const float* x  = (const float*)d_in[0];
    const float* gw = (const float*)d_in[1];
    const float* gb = (const float*)d_in[2];
    const float* pw = (const float*)d_in[3];
    const float* pb = (const float*)d_in[4];
    float* out = (float*)d_out;

    const int smem_bytes = SMEM_FLOATS * 4;   // 208,896 B
    cudaFuncSetAttribute(softtree_gemm_mma,
                         cudaFuncAttributeMaxDynamicSharedMemorySize, smem_bytes);

    softtree_gates_kernel<<<N_BATCH / K1_ROWS, 256>>>(x, gw, gb);

    dim3 grid(N_BATCH / BM, N_OUT);
    softtree_gemm_mma<<<grid, 256, smem_bytes>>>(x, pw, pb, out);
}

// round 8
// speedup vs baseline: 1.3571x; 1.2277x over previous
#include <cuda_runtime.h>
#include <cstdint>

// SoftTree: x[4096,512], gw[512,255], gb[255], pw[64,512,256], pb[64,256]
// out[b,o] = sum_l leafp[b,l] * ((x @ pw[o])[b,l] + pb[o,l])
//
// R8: fragment-order operand repacking.
//  - Prep packs x -> d_xt2 as per-thread A-frag float4 quads (rna-rounded),
//    pw -> d_pwp as per-thread B-frag float2 pairs (rna-rounded).
//  - GEMM (8 warps, 64x64 warp tile, CTA 128x256, BK=32, 4-stage cp.async
//    ring, 1 barrier/stage) loads 1 LDS.128 per A-frag and 1 LDS.64 per
//    B-frag: 12 feed instrs per 32 MMAs (was 32 LDS + 32-48 cvt).

#define N_BATCH   4096
#define N_IN      512
#define N_OUT     64
#define N_LEAF    256
#define N_GATE    255
#define TREE_DEPTH 8

__device__ float  d_leafp[N_BATCH * N_LEAF];                 // 4 MB
__device__ float4 d_xt2[(N_BATCH / 128) * 16 * 1024];        // 8 MB  (A quads)
__device__ float2 d_pwp[(size_t)N_OUT * 16 * 4096];          // 33.5 MB (B pairs)

__device__ __forceinline__ float rna_tf32(float f) {
    uint32_t u;
    asm("cvt.rna.tf32.f32 %0, %1;" : "=r"(u) : "f"(f));
    return __uint_as_float(u);
}
__device__ __forceinline__ uint32_t smem_u32(const void* p) {
    uint32_t a;
    asm("{ .reg .u64 t; cvta.to.shared.u64 t, %1; cvt.u32.u64 %0, t; }"
        : "=r"(a) : "l"(p));
    return a;
}

#define CP_ASYNC16(dst_u32, src_ptr) \
    asm volatile("cp.async.cg.shared.global [%0], [%1], 16;" \
                 :: "r"(dst_u32), "l"(src_ptr))
#define CP_COMMIT()  asm volatile("cp.async.commit_group;" ::: "memory")
#define CP_WAIT2()   asm volatile("cp.async.wait_group 2;" ::: "memory")

__device__ __forceinline__ void mma_tf32(float* d, const uint32_t* a,
                                         const uint32_t* b) {
    asm volatile(
        "mma.sync.aligned.m16n8k8.row.col.f32.tf32.tf32.f32 "
        "{%0,%1,%2,%3}, {%4,%5,%6,%7}, {%8,%9}, {%0,%1,%2,%3};"
        : "+f"(d[0]), "+f"(d[1]), "+f"(d[2]), "+f"(d[3])
        : "r"(a[0]), "r"(a[1]), "r"(a[2]), "r"(a[3]), "r"(b[0]), "r"(b[1]));
}

// ---------------------------------------------------------------------------
// P0: x -> A-frag quads.  Quad (bt,kt,mb,ks,lq,lr):
//   rows b = bt*128 + mb*16 + lq (+8), cols k = kt*32 + ks*8 + lr (+4)
//   float4 = { x[b][k], x[b+8][k], x[b][k+4], x[b+8][k+4] }  (rna)
//   linear index = (bt*16+kt)*1024 + (mb*4+ks)*32 + lq*4 + lr
// Grid: (16 kt, 32 bt), 256 threads; each thread one quad per iter (4 iters).
// ---------------------------------------------------------------------------
__global__ __launch_bounds__(256) void xt2_kernel(const float* __restrict__ x) {
    const int kt = blockIdx.x, bt = blockIdx.y;
    #pragma unroll
    for (int it = 0; it < 4; ++it) {
        int qid = it * 256 + threadIdx.x;          // 0..1023
        int mb = qid >> 7, ks = (qid >> 5) & 3, lq = (qid >> 2) & 7, lr = qid & 3;
        int b = bt * 128 + mb * 16 + lq;
        int k = kt * 32 + ks * 8 + lr;
        const float* xb = x + (size_t)b * N_IN + k;
        float4 q;
        q.x = rna_tf32(xb[0]);
        q.y = rna_tf32(xb[8 * N_IN]);
        q.z = rna_tf32(xb[4]);
        q.w = rna_tf32(xb[8 * N_IN + 4]);
        d_xt2[(size_t)(bt * 16 + kt) * 1024 + qid] = q;
    }
}

// ---------------------------------------------------------------------------
// P1: pw -> B-frag pairs.  Pair (o,kt,ks,n,lr):
//   float2 = { pw[o][kt*32+ks*8+lr][n], pw[o][kt*32+ks*8+lr+4][n] } (rna)
//   linear = ((o*16+kt)*4+ks)*1024 + n*4 + lr
// Grid: (64 = kt*4+ks, 64 o), 256 threads (n = tid).
// ---------------------------------------------------------------------------
__global__ __launch_bounds__(256) void pwp_kernel(const float* __restrict__ pw) {
    const int o = blockIdx.y;
    const int kt = blockIdx.x >> 2, ks = blockIdx.x & 3;
    const int n = threadIdx.x;
    const int k0 = kt * 32 + ks * 8;
    const float* src = pw + ((size_t)o * N_IN + k0) * N_LEAF + n;
    float v[8];
    #pragma unroll
    for (int j = 0; j < 8; ++j) v[j] = rna_tf32(src[j * N_LEAF]);
    float2* dst = d_pwp + ((size_t)(o * 16 + kt) * 4 + ks) * 1024 + n * 4;
    #pragma unroll
    for (int lr = 0; lr < 4; ++lr)
        dst[lr] = make_float2(v[lr], v[lr + 4]);
}

// ---------------------------------------------------------------------------
// K2: gates + leaf probabilities (proven)
// ---------------------------------------------------------------------------
#define K1_ROWS 8
__global__ __launch_bounds__(256) void softtree_gates_kernel(
    const float* __restrict__ x, const float* __restrict__ gw,
    const float* __restrict__ gb)
{
    __shared__ float xs[K1_ROWS][N_IN];
    __shared__ float gs[K1_ROWS][N_LEAF];
    const int tid = threadIdx.x;
    const int b0  = blockIdx.x * K1_ROWS;

    {
        const float4* src = reinterpret_cast<const float4*>(x + (size_t)b0 * N_IN);
        float4* dst = reinterpret_cast<float4*>(&xs[0][0]);
        #pragma unroll
        for (int it = 0; it < (K1_ROWS * N_IN / 4) / 256; ++it)
            dst[it * 256 + tid] = src[it * 256 + tid];
    }
    __syncthreads();

    if (tid < N_GATE) {
        float acc[K1_ROWS];
        const float bias = gb[tid];
        #pragma unroll
        for (int r = 0; r < K1_ROWS; ++r) acc[r] = bias;
        #pragma unroll 4
        for (int i = 0; i < N_IN; ++i) {
            float w = gw[i * N_GATE + tid];
            #pragma unroll
            for (int r = 0; r < K1_ROWS; ++r)
                acc[r] = fmaf(xs[r][i], w, acc[r]);
        }
        #pragma unroll
        for (int r = 0; r < K1_ROWS; ++r)
            gs[r][tid] = 1.0f / (1.0f + expf(-acc[r]));
    }
    __syncthreads();

    const int l = tid;
    #pragma unroll
    for (int r = 0; r < K1_ROWS; ++r) {
        float p = 1.0f;
        int index = 1;
        #pragma unroll
        for (int j = 0; j < TREE_DEPTH; ++j) {
            int bit = (l >> (TREE_DEPTH - 1 - j)) & 1;
            float g = gs[r][index - 1];
            p *= bit ? (1.0f - g) : g;
            index = 2 * index + bit;
        }
        d_leafp[(size_t)(b0 + r) * N_LEAF + l] = p;
    }
}

// ---------------------------------------------------------------------------
// K3: tf32 mma.sync GEMM, fragment-order smem, fused epilogue.
// Grid (32 bt, 64 o), 256 threads (8 warps, 2m x 4n), warp tile 64x64.
// Stage = A 16KB (1024 quads) + B 32KB (4096 pairs); 4-stage ring.
// ---------------------------------------------------------------------------
#define A_STAGE_F  4096                 // floats
#define B_STAGE_F  8192
#define STAGE_FLOATS (A_STAGE_F + B_STAGE_F)   // 12288 = 48KB
#define N_STAGES 4
#define SMEM_FLOATS (N_STAGES * STAGE_FLOATS + 4 * 128)
#define N_KT 16

__global__ __launch_bounds__(256, 1) void softtree_gemm_mma(
    const float* __restrict__ pb, float* __restrict__ out)
{
    extern __shared__ float sm[];
    float* red = sm + N_STAGES * STAGE_FLOATS;   // [4][128]

    const int tid  = threadIdx.x;
    const int lane = tid & 31;
    const int wid  = tid >> 5;
    const int wm   = wid >> 2;          // 0..1
    const int wn   = wid & 3;           // 0..3
    const int lq   = lane >> 2;         // 0..7
    const int lr   = lane & 3;          // 0..3
    const int o    = blockIdx.y;
    const int bt   = blockIdx.x;
    const int b0   = bt * 128;

    const float4* __restrict__ xa_all = d_xt2 + (size_t)bt * 16 * 1024;
    const float2* __restrict__ bb_all = d_pwp + (size_t)o * 16 * 4096;

    auto load_stage = [&](int kt) {
        const int s = kt & (N_STAGES - 1);
        uint32_t a_base = smem_u32(sm + s * STAGE_FLOATS);
        uint32_t b_base = a_base + A_STAGE_F * 4;
        const float4* xa = xa_all + kt * 1024;
        const float2* bb = bb_all + kt * 4096;
        #pragma unroll
        for (int it = 0; it < 4; ++it) {
            int i = it * 256 + tid;                 // quad index 0..1023
            CP_ASYNC16(a_base + (uint32_t)i * 16, xa + i);
        }
        #pragma unroll
        for (int it = 0; it < 8; ++it) {
            int i = it * 256 + tid;                 // 16B granule = 2 pairs
            CP_ASYNC16(b_base + (uint32_t)i * 16, bb + i * 2);
        }
        CP_COMMIT();
    };

    float acc[4][8][4];
    #pragma unroll
    for (int mf = 0; mf < 4; ++mf)
        #pragma unroll
        for (int nf = 0; nf < 8; ++nf)
            #pragma unroll
            for (int e = 0; e < 4; ++e) acc[mf][nf][e] = 0.0f;

    load_stage(0);
    load_stage(1);
    load_stage(2);

    for (int kt = 0; kt < N_KT; ++kt) {
        CP_WAIT2();
        __syncthreads();
        if (kt + 3 < N_KT) load_stage(kt + 3);

        const int s = kt & (N_STAGES - 1);
        const float* Asb = sm + s * STAGE_FLOATS;
        const float* Bsb = Asb + A_STAGE_F;

        #pragma unroll
        for (int ks = 0; ks < 4; ++ks) {
            uint32_t af[4][4], bf[8][2];
            #pragma unroll
            for (int mf = 0; mf < 4; ++mf) {
                const int mb = wm * 4 + mf;
                float4 a4 = *reinterpret_cast<const float4*>(
                    Asb + ((size_t)((mb * 4 + ks) * 32 + lq * 4 + lr)) * 4);
                af[mf][0] = __float_as_uint(a4.x);
                af[mf][1] = __float_as_uint(a4.y);
                af[mf][2] = __float_as_uint(a4.z);
                af[mf][3] = __float_as_uint(a4.w);
            }
            #pragma unroll
            for (int nf = 0; nf < 8; ++nf) {
                const int n = wn * 64 + nf * 8 + lq;
                float2 b2 = *reinterpret_cast<const float2*>(
                    Bsb + ((size_t)((ks * 256 + n) * 4 + lr)) * 2);
                bf[nf][0] = __float_as_uint(b2.x);
                bf[nf][1] = __float_as_uint(b2.y);
            }
            #pragma unroll
            for (int mf = 0; mf < 4; ++mf)
                #pragma unroll
                for (int nf = 0; nf < 8; ++nf)
                    mma_tf32(acc[mf][nf], af[mf], bf[nf]);
        }
    }

    // Fused epilogue: s[row] = sum_n p[b,n]*(C[b,n] + pb[o,n])
    const float* __restrict__ pbo = pb + (size_t)o * N_LEAF;
    #pragma unroll
    for (int mf = 0; mf < 4; ++mf) {
        const int r0 = wm * 64 + mf * 16 + lq;
        const int r1 = r0 + 8;
        const float* p0row = d_leafp + (size_t)(b0 + r0) * N_LEAF;
        const float* p1row = d_leafp + (size_t)(b0 + r1) * N_LEAF;
        float s0 = 0.0f, s1 = 0.0f;
        #pragma unroll
        for (int nf = 0; nf < 8; ++nf) {
            const int n = wn * 64 + nf * 8 + 2 * lr;
            float2 pbv = *reinterpret_cast<const float2*>(pbo + n);
            float2 pa  = *reinterpret_cast<const float2*>(p0row + n);
            float2 pc  = *reinterpret_cast<const float2*>(p1row + n);
            s0 = fmaf(acc[mf][nf][0] + pbv.x, pa.x, s0);
            s0 = fmaf(acc[mf][nf][1] + pbv.y, pa.y, s0);
            s1 = fmaf(acc[mf][nf][2] + pbv.x, pc.x, s1);
            s1 = fmaf(acc[mf][nf][3] + pbv.y, pc.y, s1);
        }
        s0 += __shfl_xor_sync(0xffffffffu, s0, 1);
        s0 += __shfl_xor_sync(0xffffffffu, s0, 2);
        s1 += __shfl_xor_sync(0xffffffffu, s1, 1);
        s1 += __shfl_xor_sync(0xffffffffu, s1, 2);
        if (lr == 0) {
            red[wn * 128 + r0] = s0;
            red[wn * 128 + r1] = s1;
        }
    }
    __syncthreads();

    if (tid < 128) {
        float v = red[0 * 128 + tid] + red[1 * 128 + tid] +
                  red[2 * 128 + tid] + red[3 * 128 + tid];
        out[(size_t)(b0 + tid) * N_OUT + o] = v;
    }
}

// ---------------------------------------------------------------------------
extern "C" void kernel_launch(void* const* d_in, const int* in_sizes, int n_in,
                              void* d_out, int out_size)
{
    const float* x  = (const float*)d_in[0];
    const float* gw = (const float*)d_in[1];
    const float* gb = (const float*)d_in[2];
    const float* pw = (const float*)d_in[3];
    const float* pb = (const float*)d_in[4];
    float* out = (float*)d_out;

    const int smem_bytes = SMEM_FLOATS * 4;     // 198,656 B
    cudaFuncSetAttribute(softtree_gemm_mma,
                         cudaFuncAttributeMaxDynamicSharedMemorySize, smem_bytes);

    xt2_kernel<<<dim3(16, 32), 256>>>(x);
    pwp_kernel<<<dim3(64, 64), 256>>>(pw);
    softtree_gates_kernel<<<N_BATCH / K1_ROWS, 256>>>(x, gw, gb);

    dim3 grid(N_BATCH / 128, N_OUT);
    softtree_gemm_mma<<<grid, 256, smem_bytes>>>(pb, out);
}